// round 15
// baseline (speedup 1.0000x reference)
#include <cuda_runtime.h>
#include <cstdint>
#include <math_constants.h>

#define NN 50000
#define HH 64
#define NEE 250000
#define NB 98            // ceil(NN/512)

typedef unsigned long long ull;

// ---------------- scratch (device globals; no runtime allocation) ----------------
// slots 0..4: layer-1 types {0,1,3,5,7}; slots 5..7: layer-2 types {1,3,7}
__device__ __align__(16) float g_Q[8][NN * HH];
__device__ __align__(16) float g_K[8][NN * HH];
__device__ __align__(16) float g_V[8][NN * HH];
__device__ __align__(16) float g_O1[NN * HH];
__device__ __align__(16) float g_O2[NN * HH];
__device__ __align__(16) float g_OUT2[NN * HH];
// CSR build scratch
__device__ __align__(16) unsigned g_cnt[5][NN];
__device__ __align__(16) unsigned g_ex[5][NN];
__device__ __align__(16) unsigned g_bs[5][NB];
__device__ __align__(16) unsigned g_startv[5][NN];
__device__ __align__(16) unsigned g_cursor[5][NN];
__device__ __align__(16) float4   g_adjf[5][NEE];  // (src_bits, ea.x, ea.y, 0)

// ---------------- tables ----------------
__constant__ int c_src[9] = {0, 0, 0, 1, 1, 1, 2, 2, 3};
__constant__ int c_dst[9] = {1, 2, 3, 2, 3, 1, 3, 2, 3};
__constant__ int c_l1t[5] = {0, 1, 3, 5, 7};
__constant__ int c_l2t[3] = {1, 3, 7};
__constant__ int c_t2s[8] = {0, 1, 0, 2, 0, 3, 0, 4};
__constant__ int c_s2t[5] = {0, 1, 3, 5, 7};
__constant__ int c_l2main[6] = {0, 3, 6, 7, 8, 9};  // L2 jobs needing O2 (Q's, t7 K/V, skip)
// attn1 grouping: y=0 -> O1 (types {0,5}), y=1 -> O2 (types {1,3,7})
__constant__ int c_a1n[2] = {2, 3};
__constant__ int c_a1s[2][3] = {{0, 3, 0}, {1, 2, 4}};
__constant__ int c_a1t[2][3] = {{0, 5, 0}, {1, 3, 7}};
// attn2: OUT2 <- layer-2 slots {5,6,7} (types {1,3,7}); CSR slots {1,2,4}
__constant__ int c_a2s[3] = {5, 6, 7};
__constant__ int c_a2c[3] = {1, 2, 4};
__constant__ int c_a2t[3] = {1, 3, 7};

// ---------------- helpers ----------------
__device__ __forceinline__ void fma2(ull& a, ull x, ull w) {
    asm("fma.rn.f32x2 %0, %1, %2, %0;" : "+l"(a) : "l"(x), "l"(w));
}
__device__ __forceinline__ ull pack2(float x, float y) {
    ull r; asm("mov.b64 %0, {%1, %2};" : "=l"(r) : "f"(x), "f"(y)); return r;
}
__device__ __forceinline__ void unpack2(ull v, float& x, float& y) {
    asm("mov.b64 {%0, %1}, %2;" : "=f"(x), "=f"(y) : "l"(v));
}

// ---------------- init: only CSR counters need zeroing ----------------
__global__ void init_kernel() {
    int i = (blockIdx.x * 256 + threadIdx.x) * 4;
    if (i < 5 * NN) *(uint4*)(&g_cnt[0][0] + i) = make_uint4(0u, 0u, 0u, 0u);
}

// ---------------- CSR build ----------------
__global__ void __launch_bounds__(256) count_kernel(const int* __restrict__ EI) {
    int slot = blockIdx.y, t = c_s2t[slot];
    int eid = blockIdx.x * 256 + threadIdx.x;
    if (eid >= NEE) return;
    int dst = EI[t * 2 * NEE + NEE + eid];
    atomicAdd(&g_cnt[slot][dst], 1u);
}

__global__ void __launch_bounds__(512) scan1_kernel() {
    int slot = blockIdx.y;
    int i = blockIdx.x * 512 + threadIdx.x;
    unsigned v = (i < NN) ? g_cnt[slot][i] : 0u;
    __shared__ unsigned s[512];
    s[threadIdx.x] = v;
    __syncthreads();
    #pragma unroll
    for (int off = 1; off < 512; off <<= 1) {
        unsigned t = (threadIdx.x >= off) ? s[threadIdx.x - off] : 0u;
        __syncthreads();
        s[threadIdx.x] += t;
        __syncthreads();
    }
    if (i < NN) g_ex[slot][i] = s[threadIdx.x] - v;
    if (threadIdx.x == 511) g_bs[slot][blockIdx.x] = s[511];
}

__global__ void __launch_bounds__(512) scan3_kernel() {
    int slot = blockIdx.y;
    __shared__ unsigned sOff;
    if (threadIdx.x == 0) sOff = 0u;
    __syncthreads();
    if (threadIdx.x < 128) {
        unsigned v = (threadIdx.x < (unsigned)blockIdx.x && threadIdx.x < NB)
                     ? g_bs[slot][threadIdx.x] : 0u;
        #pragma unroll
        for (int off = 16; off > 0; off >>= 1)
            v += __shfl_xor_sync(0xffffffffu, v, off);
        if ((threadIdx.x & 31) == 0) atomicAdd(&sOff, v);
    }
    __syncthreads();
    unsigned base = sOff;
    int i = blockIdx.x * 512 + threadIdx.x;
    if (i < NN) {
        unsigned st = g_ex[slot][i] + base;
        g_startv[slot][i] = st;
        g_cursor[slot][i] = st;
    }
}

__global__ void __launch_bounds__(256) scatter_kernel(
    const int* __restrict__ EI, const float* __restrict__ EA)
{
    int slot = blockIdx.y, t = c_s2t[slot];
    int eid = blockIdx.x * 256 + threadIdx.x;
    if (eid >= NEE) return;
    int src = EI[t * 2 * NEE + eid];
    int dst = EI[t * 2 * NEE + NEE + eid];
    float2 ea = *(const float2*)(EA + (size_t)t * NEE * 2 + eid * 2);  // coalesced
    unsigned pos = atomicAdd(&g_cursor[slot][dst], 1u);
    g_adjf[slot][pos] = make_float4(__int_as_float(src), ea.x, ea.y, 0.f);
}

// ---------------- GEMM: 8x8 blocking (R12 core; mode selects job subset) --------
// mode 0: layer0, 17 jobs (15 QKV + O1 skip + O2 skip)
// mode 1: layer1 main, 6 jobs {t1Q,t3Q,t7Q,t7K,t7V,skip}  (need O2/O1)
// mode 2: layer1 t1 K/V (jobs 1,2; input x0 — no deps)
// mode 3: layer1 t3 K/V (jobs 4,5; input relu(O1))
__global__ void __launch_bounds__(128, 4) gemm_kernel(
    const float* __restrict__ x0, const float* __restrict__ x1,
    const float* __restrict__ x2, const float* __restrict__ x3,
    const float* __restrict__ Wq, const float* __restrict__ bq,
    const float* __restrict__ Wk, const float* __restrict__ bk,
    const float* __restrict__ Wv, const float* __restrict__ bv,
    const float* __restrict__ Ws, const float* __restrict__ bs,
    int mode)
{
    __shared__ __align__(16) float sW[64 * 64];
    __shared__ __align__(16) float sX[64 * 128];

    int layer = (mode != 0);
    int job;
    if (mode == 0)      job = blockIdx.y;
    else if (mode == 1) job = c_l2main[blockIdx.y];
    else if (mode == 2) job = 1 + blockIdx.y;
    else                job = 4 + blockIdx.y;

    int ntyp = layer ? 3 : 5;
    const int* tl = layer ? c_l2t : c_l1t;

    const float *Wp0, *Wp1 = nullptr, *Wp2 = nullptr;
    const float *Bp0, *Bp1 = nullptr, *Bp2 = nullptr;
    const float* X; bool reluX = false; float* OUT;

    if (job < 3 * ntyp) {
        int ti = job / 3, role = job % 3;
        int t = tl[ti];
        int slot = layer ? (5 + ti) : c_t2s[t];
        int insel = (role == 0) ? c_dst[t] : c_src[t];
        if (layer) {
            X = (insel == 0) ? x0 : (insel == 1) ? g_O1 : g_O2;
            reluX = (insel != 0);
        } else {
            X = (insel == 0) ? x0 : (insel == 1) ? x1 : (insel == 2) ? x2 : x3;
        }
        int wo = layer * 9 + t;
        if (role == 0)      { Wp0 = Wq + wo * 4096; Bp0 = bq + wo * 64; OUT = g_Q[slot]; }
        else if (role == 1) { Wp0 = Wk + wo * 4096; Bp0 = bk + wo * 64; OUT = g_K[slot]; }
        else                { Wp0 = Wv + wo * 4096; Bp0 = bv + wo * 64; OUT = g_V[slot]; }
    } else {
        if (!layer) {
            if (job == 15) {  // O1 skip: types 0,5; input x1
                Wp0 = Ws + 0 * 4096; Wp1 = Ws + 5 * 4096;
                Bp0 = bs + 0 * 64;   Bp1 = bs + 5 * 64;
                X = x1; OUT = g_O1;
            } else {          // O2 skip: types 1,3,7; input x2
                Wp0 = Ws + 1 * 4096; Wp1 = Ws + 3 * 4096; Wp2 = Ws + 7 * 4096;
                Bp0 = bs + 1 * 64;   Bp1 = bs + 3 * 64;   Bp2 = bs + 7 * 64;
                X = x2; OUT = g_O2;
            }
        } else {              // OUT2 skip: layer-2 types 1,3,7; input relu(O2)
            Wp0 = Ws + 10 * 4096; Wp1 = Ws + 12 * 4096; Wp2 = Ws + 16 * 4096;
            Bp0 = bs + 10 * 64;   Bp1 = bs + 12 * 64;   Bp2 = bs + 16 * 64;
            X = g_O2; reluX = true; OUT = g_OUT2;
        }
    }

    int tid = threadIdx.x;
    int row0 = blockIdx.x * 128;

    // stage W (summed for skip jobs)
    for (int i = tid * 4; i < 4096; i += 512) {
        float4 v = *(const float4*)(Wp0 + i);
        if (Wp1) {
            float4 u = *(const float4*)(Wp1 + i);
            v.x += u.x; v.y += u.y; v.z += u.z; v.w += u.w;
        }
        if (Wp2) {
            float4 u = *(const float4*)(Wp2 + i);
            v.x += u.x; v.y += u.y; v.z += u.z; v.w += u.w;
        }
        *(float4*)(sW + i) = v;
    }
    // stage X transposed with XOR swizzle
    for (int i = tid; i < 128 * 16; i += 128) {
        int rl = i >> 4, kq = (i & 15) * 4;
        int r = row0 + rl;
        float4 v = make_float4(0.f, 0.f, 0.f, 0.f);
        if (r < NN) v = *(const float4*)(X + (size_t)r * 64 + kq);
        if (reluX) {
            v.x = fmaxf(v.x, 0.f); v.y = fmaxf(v.y, 0.f);
            v.z = fmaxf(v.z, 0.f); v.w = fmaxf(v.w, 0.f);
        }
        sX[(kq + 0) * 128 + (rl ^ ((kq + 0) & 30))] = v.x;
        sX[(kq + 1) * 128 + (rl ^ ((kq + 1) & 30))] = v.y;
        sX[(kq + 2) * 128 + (rl ^ ((kq + 2) & 30))] = v.z;
        sX[(kq + 3) * 128 + (rl ^ ((kq + 3) & 30))] = v.w;
    }
    __syncthreads();

    int cgp = tid & 7;
    int rgp = tid >> 3;
    int c0 = cgp * 8;
    int rb = rgp * 8;

    ull acc[4][8];
    {
        float4 b0 = *(const float4*)(Bp0 + c0);
        float4 b1 = *(const float4*)(Bp0 + c0 + 4);
        if (Bp1) {
            float4 u0 = *(const float4*)(Bp1 + c0);
            float4 u1 = *(const float4*)(Bp1 + c0 + 4);
            b0.x += u0.x; b0.y += u0.y; b0.z += u0.z; b0.w += u0.w;
            b1.x += u1.x; b1.y += u1.y; b1.z += u1.z; b1.w += u1.w;
        }
        if (Bp2) {
            float4 u0 = *(const float4*)(Bp2 + c0);
            float4 u1 = *(const float4*)(Bp2 + c0 + 4);
            b0.x += u0.x; b0.y += u0.y; b0.z += u0.z; b0.w += u0.w;
            b1.x += u1.x; b1.y += u1.y; b1.z += u1.z; b1.w += u1.w;
        }
        ull bb[8];
        bb[0] = pack2(b0.x, b0.x); bb[1] = pack2(b0.y, b0.y);
        bb[2] = pack2(b0.z, b0.z); bb[3] = pack2(b0.w, b0.w);
        bb[4] = pack2(b1.x, b1.x); bb[5] = pack2(b1.y, b1.y);
        bb[6] = pack2(b1.z, b1.z); bb[7] = pack2(b1.w, b1.w);
        #pragma unroll
        for (int rp = 0; rp < 4; rp++)
            #pragma unroll
            for (int c = 0; c < 8; c++) acc[rp][c] = bb[c];
    }

    #define WCOL(wval, c, xs0, xs1, xs2, xs3)                        \
        { ull wb_ = pack2(wval, wval);                               \
          fma2(acc[0][c], xs0, wb_); fma2(acc[1][c], xs1, wb_);      \
          fma2(acc[2][c], xs2, wb_); fma2(acc[3][c], xs3, wb_); }

    const float* sWc = sW + c0;
    #pragma unroll 2
    for (int m = 0; m < 32; m++) {
        int k = 2 * m;
        int sw = k & 30;
        const float* xr = sX + k * 128;
        const float* xq0 = xr + ((rb + 0) ^ sw);
        const float* xq1 = xr + ((rb + 2) ^ sw);
        const float* xq2 = xr + ((rb + 4) ^ sw);
        const float* xq3 = xr + ((rb + 6) ^ sw);
        ull xa0 = *(const ull*)xq0,         xa1 = *(const ull*)xq1;
        ull xa2 = *(const ull*)xq2,         xa3 = *(const ull*)xq3;
        ull xb0 = *(const ull*)(xq0 + 128), xb1 = *(const ull*)(xq1 + 128);
        ull xb2 = *(const ull*)(xq2 + 128), xb3 = *(const ull*)(xq3 + 128);
        const float* wr = sWc + k * 64;
        float4 wA0 = *(const float4*)(wr);
        float4 wA1 = *(const float4*)(wr + 4);
        float4 wB0 = *(const float4*)(wr + 64);
        float4 wB1 = *(const float4*)(wr + 68);

        WCOL(wA0.x, 0, xa0, xa1, xa2, xa3)
        WCOL(wA0.y, 1, xa0, xa1, xa2, xa3)
        WCOL(wA0.z, 2, xa0, xa1, xa2, xa3)
        WCOL(wA0.w, 3, xa0, xa1, xa2, xa3)
        WCOL(wA1.x, 4, xa0, xa1, xa2, xa3)
        WCOL(wA1.y, 5, xa0, xa1, xa2, xa3)
        WCOL(wA1.z, 6, xa0, xa1, xa2, xa3)
        WCOL(wA1.w, 7, xa0, xa1, xa2, xa3)
        WCOL(wB0.x, 0, xb0, xb1, xb2, xb3)
        WCOL(wB0.y, 1, xb0, xb1, xb2, xb3)
        WCOL(wB0.z, 2, xb0, xb1, xb2, xb3)
        WCOL(wB0.w, 3, xb0, xb1, xb2, xb3)
        WCOL(wB1.x, 4, xb0, xb1, xb2, xb3)
        WCOL(wB1.y, 5, xb0, xb1, xb2, xb3)
        WCOL(wB1.z, 6, xb0, xb1, xb2, xb3)
        WCOL(wB1.w, 7, xb0, xb1, xb2, xb3)
    }
    #undef WCOL

    #pragma unroll
    for (int rp = 0; rp < 4; rp++) {
        int rA = row0 + rb + 2 * rp;
        float lo[8], hi[8];
        #pragma unroll
        for (int c = 0; c < 8; c++) unpack2(acc[rp][c], lo[c], hi[c]);
        if (rA < NN) {
            float* o = OUT + (size_t)rA * 64 + c0;
            *(float4*)(o)     = make_float4(lo[0], lo[1], lo[2], lo[3]);
            *(float4*)(o + 4) = make_float4(lo[4], lo[5], lo[6], lo[7]);
        }
        if (rA + 1 < NN) {
            float* o = OUT + (size_t)(rA + 1) * 64 + c0;
            *(float4*)(o)     = make_float4(hi[0], hi[1], hi[2], hi[3]);
            *(float4*)(o + 4) = make_float4(hi[4], hi[5], hi[6], hi[7]);
        }
    }
}

// ------- per-type 4-wide online-softmax core; qkv slot + csr slot separate -------
__device__ __forceinline__ void attn_type(
    int slot, int cslot, const float* sWeT, int d0, bool valid, int lane,
    unsigned gmask, float4& os0, float4& os1)
{
    unsigned start = g_startv[cslot][d0];
    unsigned end = (d0 == NN - 1) ? (unsigned)NEE : g_startv[cslot][d0 + 1];
    if (!valid || end <= start) return;

    const float4* Q4 = (const float4*)(g_Q[slot] + (size_t)d0 * 64 + lane * 8);
    float4 q0 = Q4[0], q1 = Q4[1];
    float4 w0a = ((const float4*)sWeT)[lane * 2];
    float4 w0b = ((const float4*)sWeT)[lane * 2 + 1];
    float4 w1a = ((const float4*)(sWeT + 64))[lane * 2];
    float4 w1b = ((const float4*)(sWeT + 64))[lane * 2 + 1];

    float qe0 = q0.x * w0a.x + q0.y * w0a.y + q0.z * w0a.z + q0.w * w0a.w
              + q1.x * w0b.x + q1.y * w0b.y + q1.z * w0b.z + q1.w * w0b.w;
    float qe1 = q0.x * w1a.x + q0.y * w1a.y + q0.z * w1a.z + q0.w * w1a.w
              + q1.x * w1b.x + q1.y * w1b.y + q1.z * w1b.z + q1.w * w1b.w;
    #pragma unroll
    for (int off = 1; off < 8; off <<= 1) {
        qe0 += __shfl_xor_sync(gmask, qe0, off);
        qe1 += __shfl_xor_sync(gmask, qe1, off);
    }

    const float4* adj = g_adjf[cslot];
    const float* Kb = g_K[slot];
    const float* Vb = g_V[slot];

    float m = -CUDART_INF_F, den = 0.f, Sx = 0.f, Sy = 0.f;
    float4 a0 = make_float4(0, 0, 0, 0), a1 = a0;

    for (unsigned j = start; j < end; j += 4) {
        unsigned em1 = end - 1;
        unsigned i1 = min(j + 1, em1), i2 = min(j + 2, em1), i3 = min(j + 3, em1);
        bool v1 = (j + 1 < end), v2 = (j + 2 < end), v3 = (j + 3 < end);

        float4 r0 = adj[j], r1 = adj[i1], r2 = adj[i2], r3 = adj[i3];
        int src0 = __float_as_int(r0.x), src1 = __float_as_int(r1.x);
        int src2 = __float_as_int(r2.x), src3 = __float_as_int(r3.x);

        const float4* K0 = (const float4*)(Kb + (size_t)src0 * 64 + lane * 8);
        const float4* K1 = (const float4*)(Kb + (size_t)src1 * 64 + lane * 8);
        const float4* K2 = (const float4*)(Kb + (size_t)src2 * 64 + lane * 8);
        const float4* K3 = (const float4*)(Kb + (size_t)src3 * 64 + lane * 8);
        float4 k00 = K0[0], k01 = K0[1];
        float4 k10 = K1[0], k11 = K1[1];
        float4 k20 = K2[0], k21 = K2[1];
        float4 k30 = K3[0], k31 = K3[1];

        float qk0 = q0.x * k00.x, qk1 = q0.x * k10.x, qk2 = q0.x * k20.x, qk3 = q0.x * k30.x;
        qk0 = fmaf(q0.y, k00.y, qk0); qk1 = fmaf(q0.y, k10.y, qk1);
        qk2 = fmaf(q0.y, k20.y, qk2); qk3 = fmaf(q0.y, k30.y, qk3);
        qk0 = fmaf(q0.z, k00.z, qk0); qk1 = fmaf(q0.z, k10.z, qk1);
        qk2 = fmaf(q0.z, k20.z, qk2); qk3 = fmaf(q0.z, k30.z, qk3);
        qk0 = fmaf(q0.w, k00.w, qk0); qk1 = fmaf(q0.w, k10.w, qk1);
        qk2 = fmaf(q0.w, k20.w, qk2); qk3 = fmaf(q0.w, k30.w, qk3);
        qk0 = fmaf(q1.x, k01.x, qk0); qk1 = fmaf(q1.x, k11.x, qk1);
        qk2 = fmaf(q1.x, k21.x, qk2); qk3 = fmaf(q1.x, k31.x, qk3);
        qk0 = fmaf(q1.y, k01.y, qk0); qk1 = fmaf(q1.y, k11.y, qk1);
        qk2 = fmaf(q1.y, k21.y, qk2); qk3 = fmaf(q1.y, k31.y, qk3);
        qk0 = fmaf(q1.z, k01.z, qk0); qk1 = fmaf(q1.z, k11.z, qk1);
        qk2 = fmaf(q1.z, k21.z, qk2); qk3 = fmaf(q1.z, k31.z, qk3);
        qk0 = fmaf(q1.w, k01.w, qk0); qk1 = fmaf(q1.w, k11.w, qk1);
        qk2 = fmaf(q1.w, k21.w, qk2); qk3 = fmaf(q1.w, k31.w, qk3);

        #pragma unroll
        for (int off = 1; off < 8; off <<= 1) {
            qk0 += __shfl_xor_sync(gmask, qk0, off);
            qk1 += __shfl_xor_sync(gmask, qk1, off);
            qk2 += __shfl_xor_sync(gmask, qk2, off);
            qk3 += __shfl_xor_sync(gmask, qk3, off);
        }
        float al0 = fmaf(r0.y, qe0, fmaf(r0.z, qe1, qk0)) * 0.125f;
        float al1 = v1 ? fmaf(r1.y, qe0, fmaf(r1.z, qe1, qk1)) * 0.125f : -CUDART_INF_F;
        float al2 = v2 ? fmaf(r2.y, qe0, fmaf(r2.z, qe1, qk2)) * 0.125f : -CUDART_INF_F;
        float al3 = v3 ? fmaf(r3.y, qe0, fmaf(r3.z, qe1, qk3)) * 0.125f : -CUDART_INF_F;

        const float4* V0 = (const float4*)(Vb + (size_t)src0 * 64 + lane * 8);
        const float4* V1 = (const float4*)(Vb + (size_t)src1 * 64 + lane * 8);
        const float4* V2 = (const float4*)(Vb + (size_t)src2 * 64 + lane * 8);
        const float4* V3 = (const float4*)(Vb + (size_t)src3 * 64 + lane * 8);
        float4 v00 = V0[0], v01 = V0[1];
        float4 v10 = V1[0], v11 = V1[1];
        float4 v20 = V2[0], v21 = V2[1];
        float4 v30 = V3[0], v31 = V3[1];

        float nm = fmaxf(m, fmaxf(fmaxf(al0, al1), fmaxf(al2, al3)));
        float sc = __expf(m - nm);
        float w0 = __expf(al0 - nm);
        float w1 = __expf(al1 - nm);
        float w2 = __expf(al2 - nm);
        float w3 = __expf(al3 - nm);
        m = nm;
        den = fmaf(den, sc, (w0 + w1) + (w2 + w3));
        Sx = fmaf(Sx, sc, fmaf(w0, r0.y, fmaf(w1, r1.y, fmaf(w2, r2.y, w3 * r3.y))));
        Sy = fmaf(Sy, sc, fmaf(w0, r0.z, fmaf(w1, r1.z, fmaf(w2, r2.z, w3 * r3.z))));

        a0.x = fmaf(a0.x, sc, fmaf(w0, v00.x, fmaf(w1, v10.x, fmaf(w2, v20.x, w3 * v30.x))));
        a0.y = fmaf(a0.y, sc, fmaf(w0, v00.y, fmaf(w1, v10.y, fmaf(w2, v20.y, w3 * v30.y))));
        a0.z = fmaf(a0.z, sc, fmaf(w0, v00.z, fmaf(w1, v10.z, fmaf(w2, v20.z, w3 * v30.z))));
        a0.w = fmaf(a0.w, sc, fmaf(w0, v00.w, fmaf(w1, v10.w, fmaf(w2, v20.w, w3 * v30.w))));
        a1.x = fmaf(a1.x, sc, fmaf(w0, v01.x, fmaf(w1, v11.x, fmaf(w2, v21.x, w3 * v31.x))));
        a1.y = fmaf(a1.y, sc, fmaf(w0, v01.y, fmaf(w1, v11.y, fmaf(w2, v21.y, w3 * v31.y))));
        a1.z = fmaf(a1.z, sc, fmaf(w0, v01.z, fmaf(w1, v11.z, fmaf(w2, v21.z, w3 * v31.z))));
        a1.w = fmaf(a1.w, sc, fmaf(w0, v01.w, fmaf(w1, v11.w, fmaf(w2, v21.w, w3 * v31.w))));
    }

    float inv = 1.f / (den + 1e-16f);
    os0.x += fmaf(Sx, w0a.x, fmaf(Sy, w1a.x, a0.x)) * inv;
    os0.y += fmaf(Sx, w0a.y, fmaf(Sy, w1a.y, a0.y)) * inv;
    os0.z += fmaf(Sx, w0a.z, fmaf(Sy, w1a.z, a0.z)) * inv;
    os0.w += fmaf(Sx, w0a.w, fmaf(Sy, w1a.w, a0.w)) * inv;
    os1.x += fmaf(Sx, w0b.x, fmaf(Sy, w1b.x, a1.x)) * inv;
    os1.y += fmaf(Sx, w0b.y, fmaf(Sy, w1b.y, a1.y)) * inv;
    os1.z += fmaf(Sx, w0b.z, fmaf(Sy, w1b.z, a1.z)) * inv;
    os1.w += fmaf(Sx, w0b.w, fmaf(Sy, w1b.w, a1.w)) * inv;
}

// ---------------- attn layer 1: y passed as param (split launches) ----------------
__global__ void __launch_bounds__(128) attn1_kernel(const float* __restrict__ We, int y) {
    int nt = c_a1n[y];
    __shared__ __align__(16) float sWe[384];
    if (threadIdx.x < 32 * nt) {
        int ti = threadIdx.x >> 5, li = threadIdx.x & 31;
        ((float4*)(sWe + ti * 128))[li] =
            ((const float4*)(We + c_a1t[y][ti] * 128))[li];
    }
    __syncthreads();

    int lane = threadIdx.x & 7;
    unsigned gmask = 0xFFu << (threadIdx.x & 24);
    int dst = blockIdx.x * 16 + (threadIdx.x >> 3);
    bool valid = dst < NN;
    int d0 = valid ? dst : 0;

    float4 os0 = make_float4(0, 0, 0, 0), os1 = os0;
    for (int ti = 0; ti < nt; ti++)
        attn_type(c_a1s[y][ti], c_a1s[y][ti], sWe + ti * 128, d0, valid, lane, gmask, os0, os1);

    if (valid) {
        float* Or = (y ? g_O2 : g_O1) + (size_t)d0 * 64 + lane * 8;
        float4 c0v = *(float4*)Or;
        float4 c1v = *(float4*)(Or + 4);
        c0v.x += os0.x; c0v.y += os0.y; c0v.z += os0.z; c0v.w += os0.w;
        c1v.x += os1.x; c1v.y += os1.y; c1v.z += os1.z; c1v.w += os1.w;
        *(float4*)Or = c0v;
        *(float4*)(Or + 4) = c1v;
    }
}

// ---------------- attn layer 2 + fused final linear ----------------
__global__ void __launch_bounds__(128) attn2_final_kernel(
    const float* __restrict__ We, const float* __restrict__ linW,
    const float* __restrict__ linb, float* __restrict__ out)
{
    __shared__ __align__(16) float sWe[384];
    __shared__ __align__(16) float4 sLW[64];
    if (threadIdx.x < 96) {
        int ti = threadIdx.x >> 5, li = threadIdx.x & 31;
        ((float4*)(sWe + ti * 128))[li] =
            ((const float4*)(We + (9 + c_a2t[ti]) * 128))[li];
    }
    if (threadIdx.x >= 96 && threadIdx.x < 96 + 32) {
        int li = threadIdx.x - 96;
        sLW[li * 2]     = *(const float4*)(linW + li * 8);
        sLW[li * 2 + 1] = *(const float4*)(linW + li * 8 + 4);
    }
    __syncthreads();

    int lane = threadIdx.x & 7;
    unsigned gmask = 0xFFu << (threadIdx.x & 24);
    int dst = blockIdx.x * 16 + (threadIdx.x >> 3);
    bool valid = dst < NN;
    int d0 = valid ? dst : 0;

    float4 os0 = make_float4(0, 0, 0, 0), os1 = os0;
    #pragma unroll
    for (int ti = 0; ti < 3; ti++)
        attn_type(c_a2s[ti], c_a2c[ti], sWe + ti * 128, d0, valid, lane, gmask, os0, os1);

    if (valid) {
        const float* Or = g_OUT2 + (size_t)d0 * 64 + lane * 8;
        float4 c0v = *(const float4*)Or;
        float4 c1v = *(const float4*)(Or + 4);
        float h[8];
        h[0] = fmaxf(c0v.x + os0.x, 0.f); h[1] = fmaxf(c0v.y + os0.y, 0.f);
        h[2] = fmaxf(c0v.z + os0.z, 0.f); h[3] = fmaxf(c0v.w + os0.w, 0.f);
        h[4] = fmaxf(c1v.x + os1.x, 0.f); h[5] = fmaxf(c1v.y + os1.y, 0.f);
        h[6] = fmaxf(c1v.z + os1.z, 0.f); h[7] = fmaxf(c1v.w + os1.w, 0.f);
        float4 acc = make_float4(0, 0, 0, 0);
        #pragma unroll
        for (int c = 0; c < 8; c++) {
            float4 wv = sLW[lane * 8 + c];
            acc.x = fmaf(h[c], wv.x, acc.x);
            acc.y = fmaf(h[c], wv.y, acc.y);
            acc.z = fmaf(h[c], wv.z, acc.z);
            acc.w = fmaf(h[c], wv.w, acc.w);
        }
        #pragma unroll
        for (int off = 1; off < 8; off <<= 1) {
            acc.x += __shfl_xor_sync(gmask, acc.x, off);
            acc.y += __shfl_xor_sync(gmask, acc.y, off);
            acc.z += __shfl_xor_sync(gmask, acc.z, off);
            acc.w += __shfl_xor_sync(gmask, acc.w, off);
        }
        if (lane == 0) {
            float4 b = *(const float4*)linb;
            acc.x += b.x; acc.y += b.y; acc.z += b.z; acc.w += b.w;
            *(float4*)(out + (size_t)d0 * 4) = acc;
        }
    }
}

// ---------------- launcher: CSR + independent L2 K/V on side stream -------------
extern "C" void kernel_launch(void* const* d_in, const int* in_sizes, int n_in,
                              void* d_out, int out_size) {
    (void)in_sizes; (void)n_in; (void)out_size;
    const float* x0 = (const float*)d_in[0];
    const float* x1 = (const float*)d_in[1];
    const float* x2 = (const float*)d_in[2];
    const float* x3 = (const float*)d_in[3];
    const int*   EI = (const int*)d_in[4];
    const float* EA = (const float*)d_in[5];
    const float* Wq = (const float*)d_in[6];
    const float* bq = (const float*)d_in[7];
    const float* Wk = (const float*)d_in[8];
    const float* bk = (const float*)d_in[9];
    const float* Wv = (const float*)d_in[10];
    const float* bv = (const float*)d_in[11];
    const float* We = (const float*)d_in[12];
    const float* Ws = (const float*)d_in[13];
    const float* bs = (const float*)d_in[14];
    const float* lW = (const float*)d_in[15];
    const float* lb = (const float*)d_in[16];
    float* out = (float*)d_out;

    const int ROWB = (NN + 127) / 128;   // 391
    const int EB   = (NEE + 255) / 256;  // 977
    const int DB   = (NN + 15) / 16;     // 3125

    // one-time host-side resources (no device allocation)
    static cudaStream_t s2 = nullptr;
    static cudaEvent_t eFork = nullptr, eJoin = nullptr, eY0 = nullptr, eKV3 = nullptr;
    if (s2 == nullptr) {
        cudaStreamCreateWithFlags(&s2, cudaStreamNonBlocking);
        cudaEventCreateWithFlags(&eFork, cudaEventDisableTiming);
        cudaEventCreateWithFlags(&eJoin, cudaEventDisableTiming);
        cudaEventCreateWithFlags(&eY0, cudaEventDisableTiming);
        cudaEventCreateWithFlags(&eKV3, cudaEventDisableTiming);
    }

    init_kernel<<<245, 256>>>();                                             // 0 (main)
    cudaEventRecord(eFork, 0);
    cudaStreamWaitEvent(s2, eFork, 0);

    count_kernel<<<dim3(EB, 5), 256, 0, s2>>>(EI);                           // 1
    scan1_kernel<<<dim3(NB, 5), 512, 0, s2>>>();                             // 2
    gemm_kernel<<<dim3(ROWB, 17), 128>>>(x0, x1, x2, x3, Wq, bq, Wk, bk,
                                         Wv, bv, Ws, bs, 0);                 // 3 (main, profiled)
    scan3_kernel<<<dim3(NB, 5), 512, 0, s2>>>();                             // 4
    scatter_kernel<<<dim3(EB, 5), 256, 0, s2>>>(EI, EA);                     // 5
    // L2 t1 K/V: depends only on x0 — hide under gemm1 tail on s2
    gemm_kernel<<<dim3(ROWB, 2), 128, 0, s2>>>(x0, x1, x2, x3, Wq, bq, Wk, bk,
                                               Wv, bv, Ws, bs, 2);           // 6
    cudaEventRecord(eJoin, s2);
    cudaStreamWaitEvent(0, eJoin, 0);

    attn1_kernel<<<DB, 128>>>(We, 0);                                        // 7 (O1)
    cudaEventRecord(eY0, 0);
    cudaStreamWaitEvent(s2, eY0, 0);
    attn1_kernel<<<DB, 128>>>(We, 1);                                        // 8 (O2)
    // L2 t3 K/V: needs only relu(O1) — hide under attn1_y1 on s2
    gemm_kernel<<<dim3(ROWB, 2), 128, 0, s2>>>(x0, x1, x2, x3, Wq, bq, Wk, bk,
                                               Wv, bv, Ws, bs, 3);           // 9
    cudaEventRecord(eKV3, s2);

    gemm_kernel<<<dim3(ROWB, 6), 128>>>(x0, x1, x2, x3, Wq, bq, Wk, bk,
                                        Wv, bv, Ws, bs, 1);                  // 10 (main)
    cudaStreamWaitEvent(0, eKV3, 0);
    attn2_final_kernel<<<DB, 128>>>(We, lW, lb, out);                        // 11
}

// round 16
// speedup vs baseline: 1.0874x; 1.0874x over previous
#include <cuda_runtime.h>
#include <cstdint>
#include <math_constants.h>

#define NN 50000
#define HH 64
#define NEE 250000
#define NB 98            // ceil(NN/512)

typedef unsigned long long ull;

// ---------------- scratch (device globals; no runtime allocation) ----------------
__device__ __align__(16) float g_Q[5][NN * HH];
__device__ __align__(16) float g_K[5][NN * HH];
__device__ __align__(16) float g_V[5][NN * HH];
__device__ __align__(16) float g_O1[NN * HH];
__device__ __align__(16) float g_O2[NN * HH];
__device__ __align__(16) float g_OUT2[NN * HH];
// CSR build scratch
__device__ __align__(16) unsigned g_cnt[5][NN];
__device__ __align__(16) unsigned g_ex[5][NN];
__device__ __align__(16) unsigned g_bs[5][NB];
__device__ __align__(16) unsigned g_startv[5][NN];
__device__ __align__(16) unsigned g_cursor[5][NN];
__device__ __align__(16) float4   g_adjf[5][NEE];  // (src_bits, ea.x, ea.y, 0)

// ---------------- tables ----------------
__constant__ int c_src[9] = {0, 0, 0, 1, 1, 1, 2, 2, 3};
__constant__ int c_dst[9] = {1, 2, 3, 2, 3, 1, 3, 2, 3};
__constant__ int c_l1t[5] = {0, 1, 3, 5, 7};
__constant__ int c_l2t[3] = {1, 3, 7};
__constant__ int c_t2s[8] = {0, 1, 0, 2, 0, 3, 0, 4};
__constant__ int c_s2t[5] = {0, 1, 3, 5, 7};
// attn1: pass y -> slot y, type c_s2t[y], output c_p2o[y] (0=O1, 1=O2)
__constant__ int c_p2o[5] = {0, 1, 1, 0, 1};
// attn2: types {1,3,7}, CSR/QKV slots {1,2,4}
__constant__ int c_a2s[3] = {1, 2, 4};
__constant__ int c_a2t[3] = {1, 3, 7};

// ---------------- helpers ----------------
__device__ __forceinline__ void fma2(ull& a, ull x, ull w) {
    asm("fma.rn.f32x2 %0, %1, %2, %0;" : "+l"(a) : "l"(x), "l"(w));
}
__device__ __forceinline__ ull pack2(float x, float y) {
    ull r; asm("mov.b64 %0, {%1, %2};" : "=l"(r) : "f"(x), "f"(y)); return r;
}
__device__ __forceinline__ void unpack2(ull v, float& x, float& y) {
    asm("mov.b64 {%0, %1}, %2;" : "=f"(x), "=f"(y) : "l"(v));
}
__device__ __forceinline__ void redv4(float* p, float x, float y, float z, float w) {
    asm volatile("red.global.add.v4.f32 [%0], {%1,%2,%3,%4};"
                 :: "l"(p), "f"(x), "f"(y), "f"(z), "f"(w) : "memory");
}

// ---------------- init: only CSR counters need zeroing ----------------
__global__ void init_kernel() {
    int i = (blockIdx.x * 256 + threadIdx.x) * 4;
    if (i < 5 * NN) *(uint4*)(&g_cnt[0][0] + i) = make_uint4(0u, 0u, 0u, 0u);
}

// ---------------- CSR build ----------------
__global__ void __launch_bounds__(256) count_kernel(const int* __restrict__ EI) {
    int slot = blockIdx.y, t = c_s2t[slot];
    int eid = blockIdx.x * 256 + threadIdx.x;
    if (eid >= NEE) return;
    int dst = EI[t * 2 * NEE + NEE + eid];
    atomicAdd(&g_cnt[slot][dst], 1u);
}

__global__ void __launch_bounds__(512) scan1_kernel() {
    int slot = blockIdx.y;
    int i = blockIdx.x * 512 + threadIdx.x;
    unsigned v = (i < NN) ? g_cnt[slot][i] : 0u;
    __shared__ unsigned s[512];
    s[threadIdx.x] = v;
    __syncthreads();
    #pragma unroll
    for (int off = 1; off < 512; off <<= 1) {
        unsigned t = (threadIdx.x >= off) ? s[threadIdx.x - off] : 0u;
        __syncthreads();
        s[threadIdx.x] += t;
        __syncthreads();
    }
    if (i < NN) g_ex[slot][i] = s[threadIdx.x] - v;
    if (threadIdx.x == 511) g_bs[slot][blockIdx.x] = s[511];
}

__global__ void __launch_bounds__(512) scan3_kernel() {
    int slot = blockIdx.y;
    __shared__ unsigned sOff;
    if (threadIdx.x == 0) sOff = 0u;
    __syncthreads();
    if (threadIdx.x < 128) {
        unsigned v = (threadIdx.x < (unsigned)blockIdx.x && threadIdx.x < NB)
                     ? g_bs[slot][threadIdx.x] : 0u;
        #pragma unroll
        for (int off = 16; off > 0; off >>= 1)
            v += __shfl_xor_sync(0xffffffffu, v, off);
        if ((threadIdx.x & 31) == 0) atomicAdd(&sOff, v);
    }
    __syncthreads();
    unsigned base = sOff;
    int i = blockIdx.x * 512 + threadIdx.x;
    if (i < NN) {
        unsigned st = g_ex[slot][i] + base;
        g_startv[slot][i] = st;
        g_cursor[slot][i] = st;
    }
}

__global__ void __launch_bounds__(256) scatter_kernel(
    const int* __restrict__ EI, const float* __restrict__ EA)
{
    int slot = blockIdx.y, t = c_s2t[slot];
    int eid = blockIdx.x * 256 + threadIdx.x;
    if (eid >= NEE) return;
    int src = EI[t * 2 * NEE + eid];
    int dst = EI[t * 2 * NEE + NEE + eid];
    float2 ea = *(const float2*)(EA + (size_t)t * NEE * 2 + eid * 2);  // coalesced
    unsigned pos = atomicAdd(&g_cursor[slot][dst], 1u);
    g_adjf[slot][pos] = make_float4(__int_as_float(src), ea.x, ea.y, 0.f);
}

// ---------------- GEMM: 8x8 blocking (627us-proven core) ------------------------
// layer0: jobs 0..14 QKV (5 types), 15=O1 skip, 16=O2 skip. layer1: 0..8 QKV, 9 skip.
__global__ void __launch_bounds__(128, 4) gemm_kernel(
    const float* __restrict__ x0, const float* __restrict__ x1,
    const float* __restrict__ x2, const float* __restrict__ x3,
    const float* __restrict__ Wq, const float* __restrict__ bq,
    const float* __restrict__ Wk, const float* __restrict__ bk,
    const float* __restrict__ Wv, const float* __restrict__ bv,
    const float* __restrict__ Ws, const float* __restrict__ bs,
    int layer)
{
    __shared__ __align__(16) float sW[64 * 64];
    __shared__ __align__(16) float sX[64 * 128];

    int job = blockIdx.y;
    int ntyp = layer ? 3 : 5;
    const int* tl = layer ? c_l2t : c_l1t;

    const float *Wp0, *Wp1 = nullptr, *Wp2 = nullptr;
    const float *Bp0, *Bp1 = nullptr, *Bp2 = nullptr;
    const float* X; bool reluX = false; float* OUT;

    if (job < 3 * ntyp) {
        int ti = job / 3, role = job % 3;
        int t = tl[ti], slot = c_t2s[t];
        int insel = (role == 0) ? c_dst[t] : c_src[t];
        if (layer) {
            X = (insel == 0) ? x0 : (insel == 1) ? g_O1 : g_O2;
            reluX = (insel != 0);
        } else {
            X = (insel == 0) ? x0 : (insel == 1) ? x1 : (insel == 2) ? x2 : x3;
        }
        int wo = layer * 9 + t;
        if (role == 0)      { Wp0 = Wq + wo * 4096; Bp0 = bq + wo * 64; OUT = g_Q[slot]; }
        else if (role == 1) { Wp0 = Wk + wo * 4096; Bp0 = bk + wo * 64; OUT = g_K[slot]; }
        else                { Wp0 = Wv + wo * 4096; Bp0 = bv + wo * 64; OUT = g_V[slot]; }
    } else {
        if (!layer) {
            if (job == 15) {  // O1 skip: types 0,5; input x1
                Wp0 = Ws + 0 * 4096; Wp1 = Ws + 5 * 4096;
                Bp0 = bs + 0 * 64;   Bp1 = bs + 5 * 64;
                X = x1; OUT = g_O1;
            } else {          // O2 skip: types 1,3,7; input x2
                Wp0 = Ws + 1 * 4096; Wp1 = Ws + 3 * 4096; Wp2 = Ws + 7 * 4096;
                Bp0 = bs + 1 * 64;   Bp1 = bs + 3 * 64;   Bp2 = bs + 7 * 64;
                X = x2; OUT = g_O2;
            }
        } else {              // OUT2 skip: layer-2 types 1,3,7; input relu(O2)
            Wp0 = Ws + 10 * 4096; Wp1 = Ws + 12 * 4096; Wp2 = Ws + 16 * 4096;
            Bp0 = bs + 10 * 64;   Bp1 = bs + 12 * 64;   Bp2 = bs + 16 * 64;
            X = g_O2; reluX = true; OUT = g_OUT2;
        }
    }

    int tid = threadIdx.x;
    int row0 = blockIdx.x * 128;

    for (int i = tid * 4; i < 4096; i += 512) {
        float4 v = *(const float4*)(Wp0 + i);
        if (Wp1) {
            float4 u = *(const float4*)(Wp1 + i);
            v.x += u.x; v.y += u.y; v.z += u.z; v.w += u.w;
        }
        if (Wp2) {
            float4 u = *(const float4*)(Wp2 + i);
            v.x += u.x; v.y += u.y; v.z += u.z; v.w += u.w;
        }
        *(float4*)(sW + i) = v;
    }
    for (int i = tid; i < 128 * 16; i += 128) {
        int rl = i >> 4, kq = (i & 15) * 4;
        int r = row0 + rl;
        float4 v = make_float4(0.f, 0.f, 0.f, 0.f);
        if (r < NN) v = *(const float4*)(X + (size_t)r * 64 + kq);
        if (reluX) {
            v.x = fmaxf(v.x, 0.f); v.y = fmaxf(v.y, 0.f);
            v.z = fmaxf(v.z, 0.f); v.w = fmaxf(v.w, 0.f);
        }
        sX[(kq + 0) * 128 + (rl ^ ((kq + 0) & 30))] = v.x;
        sX[(kq + 1) * 128 + (rl ^ ((kq + 1) & 30))] = v.y;
        sX[(kq + 2) * 128 + (rl ^ ((kq + 2) & 30))] = v.z;
        sX[(kq + 3) * 128 + (rl ^ ((kq + 3) & 30))] = v.w;
    }
    __syncthreads();

    int cgp = tid & 7;
    int rgp = tid >> 3;
    int c0 = cgp * 8;
    int rb = rgp * 8;

    ull acc[4][8];
    {
        float4 b0 = *(const float4*)(Bp0 + c0);
        float4 b1 = *(const float4*)(Bp0 + c0 + 4);
        if (Bp1) {
            float4 u0 = *(const float4*)(Bp1 + c0);
            float4 u1 = *(const float4*)(Bp1 + c0 + 4);
            b0.x += u0.x; b0.y += u0.y; b0.z += u0.z; b0.w += u0.w;
            b1.x += u1.x; b1.y += u1.y; b1.z += u1.z; b1.w += u1.w;
        }
        if (Bp2) {
            float4 u0 = *(const float4*)(Bp2 + c0);
            float4 u1 = *(const float4*)(Bp2 + c0 + 4);
            b0.x += u0.x; b0.y += u0.y; b0.z += u0.z; b0.w += u0.w;
            b1.x += u1.x; b1.y += u1.y; b1.z += u1.z; b1.w += u1.w;
        }
        ull bb[8];
        bb[0] = pack2(b0.x, b0.x); bb[1] = pack2(b0.y, b0.y);
        bb[2] = pack2(b0.z, b0.z); bb[3] = pack2(b0.w, b0.w);
        bb[4] = pack2(b1.x, b1.x); bb[5] = pack2(b1.y, b1.y);
        bb[6] = pack2(b1.z, b1.z); bb[7] = pack2(b1.w, b1.w);
        #pragma unroll
        for (int rp = 0; rp < 4; rp++)
            #pragma unroll
            for (int c = 0; c < 8; c++) acc[rp][c] = bb[c];
    }

    #define WCOL(wval, c, xs0, xs1, xs2, xs3)                        \
        { ull wb_ = pack2(wval, wval);                               \
          fma2(acc[0][c], xs0, wb_); fma2(acc[1][c], xs1, wb_);      \
          fma2(acc[2][c], xs2, wb_); fma2(acc[3][c], xs3, wb_); }

    const float* sWc = sW + c0;
    #pragma unroll 2
    for (int m = 0; m < 32; m++) {
        int k = 2 * m;
        int sw = k & 30;
        const float* xr = sX + k * 128;
        const float* xq0 = xr + ((rb + 0) ^ sw);
        const float* xq1 = xr + ((rb + 2) ^ sw);
        const float* xq2 = xr + ((rb + 4) ^ sw);
        const float* xq3 = xr + ((rb + 6) ^ sw);
        ull xa0 = *(const ull*)xq0,         xa1 = *(const ull*)xq1;
        ull xa2 = *(const ull*)xq2,         xa3 = *(const ull*)xq3;
        ull xb0 = *(const ull*)(xq0 + 128), xb1 = *(const ull*)(xq1 + 128);
        ull xb2 = *(const ull*)(xq2 + 128), xb3 = *(const ull*)(xq3 + 128);
        const float* wr = sWc + k * 64;
        float4 wA0 = *(const float4*)(wr);
        float4 wA1 = *(const float4*)(wr + 4);
        float4 wB0 = *(const float4*)(wr + 64);
        float4 wB1 = *(const float4*)(wr + 68);

        WCOL(wA0.x, 0, xa0, xa1, xa2, xa3)
        WCOL(wA0.y, 1, xa0, xa1, xa2, xa3)
        WCOL(wA0.z, 2, xa0, xa1, xa2, xa3)
        WCOL(wA0.w, 3, xa0, xa1, xa2, xa3)
        WCOL(wA1.x, 4, xa0, xa1, xa2, xa3)
        WCOL(wA1.y, 5, xa0, xa1, xa2, xa3)
        WCOL(wA1.z, 6, xa0, xa1, xa2, xa3)
        WCOL(wA1.w, 7, xa0, xa1, xa2, xa3)
        WCOL(wB0.x, 0, xb0, xb1, xb2, xb3)
        WCOL(wB0.y, 1, xb0, xb1, xb2, xb3)
        WCOL(wB0.z, 2, xb0, xb1, xb2, xb3)
        WCOL(wB0.w, 3, xb0, xb1, xb2, xb3)
        WCOL(wB1.x, 4, xb0, xb1, xb2, xb3)
        WCOL(wB1.y, 5, xb0, xb1, xb2, xb3)
        WCOL(wB1.z, 6, xb0, xb1, xb2, xb3)
        WCOL(wB1.w, 7, xb0, xb1, xb2, xb3)
    }
    #undef WCOL

    #pragma unroll
    for (int rp = 0; rp < 4; rp++) {
        int rA = row0 + rb + 2 * rp;
        float lo[8], hi[8];
        #pragma unroll
        for (int c = 0; c < 8; c++) unpack2(acc[rp][c], lo[c], hi[c]);
        if (rA < NN) {
            float* o = OUT + (size_t)rA * 64 + c0;
            *(float4*)(o)     = make_float4(lo[0], lo[1], lo[2], lo[3]);
            *(float4*)(o + 4) = make_float4(lo[4], lo[5], lo[6], lo[7]);
        }
        if (rA + 1 < NN) {
            float* o = OUT + (size_t)(rA + 1) * 64 + c0;
            *(float4*)(o)     = make_float4(hi[0], hi[1], hi[2], hi[3]);
            *(float4*)(o + 4) = make_float4(hi[4], hi[5], hi[6], hi[7]);
        }
    }
}

// ------- single-type 4-wide online-softmax; red.add into pre-initialized O -------
__device__ __forceinline__ void attn_type_atomic(
    int slot, const float* sWeT, int d0, bool valid, int lane, unsigned gmask,
    float* Obase)
{
    unsigned start = g_startv[slot][d0];
    unsigned end = (d0 == NN - 1) ? (unsigned)NEE : g_startv[slot][d0 + 1];
    if (!valid || end <= start) return;

    const float4* Q4 = (const float4*)(g_Q[slot] + (size_t)d0 * 64 + lane * 8);
    float4 q0 = Q4[0], q1 = Q4[1];
    float4 w0a = ((const float4*)sWeT)[lane * 2];
    float4 w0b = ((const float4*)sWeT)[lane * 2 + 1];
    float4 w1a = ((const float4*)(sWeT + 64))[lane * 2];
    float4 w1b = ((const float4*)(sWeT + 64))[lane * 2 + 1];

    float qe0 = q0.x * w0a.x + q0.y * w0a.y + q0.z * w0a.z + q0.w * w0a.w
              + q1.x * w0b.x + q1.y * w0b.y + q1.z * w0b.z + q1.w * w0b.w;
    float qe1 = q0.x * w1a.x + q0.y * w1a.y + q0.z * w1a.z + q0.w * w1a.w
              + q1.x * w1b.x + q1.y * w1b.y + q1.z * w1b.z + q1.w * w1b.w;
    #pragma unroll
    for (int off = 1; off < 8; off <<= 1) {
        qe0 += __shfl_xor_sync(gmask, qe0, off);
        qe1 += __shfl_xor_sync(gmask, qe1, off);
    }

    const float4* adj = g_adjf[slot];
    const float* Kb = g_K[slot];
    const float* Vb = g_V[slot];

    float m = -CUDART_INF_F, den = 0.f, Sx = 0.f, Sy = 0.f;
    float4 a0 = make_float4(0, 0, 0, 0), a1 = a0;

    for (unsigned j = start; j < end; j += 4) {
        unsigned em1 = end - 1;
        unsigned i1 = min(j + 1, em1), i2 = min(j + 2, em1), i3 = min(j + 3, em1);
        bool v1 = (j + 1 < end), v2 = (j + 2 < end), v3 = (j + 3 < end);

        float4 r0 = adj[j], r1 = adj[i1], r2 = adj[i2], r3 = adj[i3];
        int src0 = __float_as_int(r0.x), src1 = __float_as_int(r1.x);
        int src2 = __float_as_int(r2.x), src3 = __float_as_int(r3.x);

        const float4* K0 = (const float4*)(Kb + (size_t)src0 * 64 + lane * 8);
        const float4* K1 = (const float4*)(Kb + (size_t)src1 * 64 + lane * 8);
        const float4* K2 = (const float4*)(Kb + (size_t)src2 * 64 + lane * 8);
        const float4* K3 = (const float4*)(Kb + (size_t)src3 * 64 + lane * 8);
        float4 k00 = K0[0], k01 = K0[1];
        float4 k10 = K1[0], k11 = K1[1];
        float4 k20 = K2[0], k21 = K2[1];
        float4 k30 = K3[0], k31 = K3[1];

        float qk0 = q0.x * k00.x, qk1 = q0.x * k10.x, qk2 = q0.x * k20.x, qk3 = q0.x * k30.x;
        qk0 = fmaf(q0.y, k00.y, qk0); qk1 = fmaf(q0.y, k10.y, qk1);
        qk2 = fmaf(q0.y, k20.y, qk2); qk3 = fmaf(q0.y, k30.y, qk3);
        qk0 = fmaf(q0.z, k00.z, qk0); qk1 = fmaf(q0.z, k10.z, qk1);
        qk2 = fmaf(q0.z, k20.z, qk2); qk3 = fmaf(q0.z, k30.z, qk3);
        qk0 = fmaf(q0.w, k00.w, qk0); qk1 = fmaf(q0.w, k10.w, qk1);
        qk2 = fmaf(q0.w, k20.w, qk2); qk3 = fmaf(q0.w, k30.w, qk3);
        qk0 = fmaf(q1.x, k01.x, qk0); qk1 = fmaf(q1.x, k11.x, qk1);
        qk2 = fmaf(q1.x, k21.x, qk2); qk3 = fmaf(q1.x, k31.x, qk3);
        qk0 = fmaf(q1.y, k01.y, qk0); qk1 = fmaf(q1.y, k11.y, qk1);
        qk2 = fmaf(q1.y, k21.y, qk2); qk3 = fmaf(q1.y, k31.y, qk3);
        qk0 = fmaf(q1.z, k01.z, qk0); qk1 = fmaf(q1.z, k11.z, qk1);
        qk2 = fmaf(q1.z, k21.z, qk2); qk3 = fmaf(q1.z, k31.z, qk3);
        qk0 = fmaf(q1.w, k01.w, qk0); qk1 = fmaf(q1.w, k11.w, qk1);
        qk2 = fmaf(q1.w, k21.w, qk2); qk3 = fmaf(q1.w, k31.w, qk3);

        #pragma unroll
        for (int off = 1; off < 8; off <<= 1) {
            qk0 += __shfl_xor_sync(gmask, qk0, off);
            qk1 += __shfl_xor_sync(gmask, qk1, off);
            qk2 += __shfl_xor_sync(gmask, qk2, off);
            qk3 += __shfl_xor_sync(gmask, qk3, off);
        }
        float al0 = fmaf(r0.y, qe0, fmaf(r0.z, qe1, qk0)) * 0.125f;
        float al1 = v1 ? fmaf(r1.y, qe0, fmaf(r1.z, qe1, qk1)) * 0.125f : -CUDART_INF_F;
        float al2 = v2 ? fmaf(r2.y, qe0, fmaf(r2.z, qe1, qk2)) * 0.125f : -CUDART_INF_F;
        float al3 = v3 ? fmaf(r3.y, qe0, fmaf(r3.z, qe1, qk3)) * 0.125f : -CUDART_INF_F;

        const float4* V0 = (const float4*)(Vb + (size_t)src0 * 64 + lane * 8);
        const float4* V1 = (const float4*)(Vb + (size_t)src1 * 64 + lane * 8);
        const float4* V2 = (const float4*)(Vb + (size_t)src2 * 64 + lane * 8);
        const float4* V3 = (const float4*)(Vb + (size_t)src3 * 64 + lane * 8);
        float4 v00 = V0[0], v01 = V0[1];
        float4 v10 = V1[0], v11 = V1[1];
        float4 v20 = V2[0], v21 = V2[1];
        float4 v30 = V3[0], v31 = V3[1];

        float nm = fmaxf(m, fmaxf(fmaxf(al0, al1), fmaxf(al2, al3)));
        float sc = __expf(m - nm);
        float w0 = __expf(al0 - nm);
        float w1 = __expf(al1 - nm);
        float w2 = __expf(al2 - nm);
        float w3 = __expf(al3 - nm);
        m = nm;
        den = fmaf(den, sc, (w0 + w1) + (w2 + w3));
        Sx = fmaf(Sx, sc, fmaf(w0, r0.y, fmaf(w1, r1.y, fmaf(w2, r2.y, w3 * r3.y))));
        Sy = fmaf(Sy, sc, fmaf(w0, r0.z, fmaf(w1, r1.z, fmaf(w2, r2.z, w3 * r3.z))));

        a0.x = fmaf(a0.x, sc, fmaf(w0, v00.x, fmaf(w1, v10.x, fmaf(w2, v20.x, w3 * v30.x))));
        a0.y = fmaf(a0.y, sc, fmaf(w0, v00.y, fmaf(w1, v10.y, fmaf(w2, v20.y, w3 * v30.y))));
        a0.z = fmaf(a0.z, sc, fmaf(w0, v00.z, fmaf(w1, v10.z, fmaf(w2, v20.z, w3 * v30.z))));
        a0.w = fmaf(a0.w, sc, fmaf(w0, v00.w, fmaf(w1, v10.w, fmaf(w2, v20.w, w3 * v30.w))));
        a1.x = fmaf(a1.x, sc, fmaf(w0, v01.x, fmaf(w1, v11.x, fmaf(w2, v21.x, w3 * v31.x))));
        a1.y = fmaf(a1.y, sc, fmaf(w0, v01.y, fmaf(w1, v11.y, fmaf(w2, v21.y, w3 * v31.y))));
        a1.z = fmaf(a1.z, sc, fmaf(w0, v01.z, fmaf(w1, v11.z, fmaf(w2, v21.z, w3 * v31.z))));
        a1.w = fmaf(a1.w, sc, fmaf(w0, v01.w, fmaf(w1, v11.w, fmaf(w2, v21.w, w3 * v31.w))));
    }

    float inv = 1.f / (den + 1e-16f);
    float* Or = Obase + (size_t)d0 * 64 + lane * 8;
    redv4(Or,
          fmaf(Sx, w0a.x, fmaf(Sy, w1a.x, a0.x)) * inv,
          fmaf(Sx, w0a.y, fmaf(Sy, w1a.y, a0.y)) * inv,
          fmaf(Sx, w0a.z, fmaf(Sy, w1a.z, a0.z)) * inv,
          fmaf(Sx, w0a.w, fmaf(Sy, w1a.w, a0.w)) * inv);
    redv4(Or + 4,
          fmaf(Sx, w0b.x, fmaf(Sy, w1b.x, a1.x)) * inv,
          fmaf(Sx, w0b.y, fmaf(Sy, w1b.y, a1.y)) * inv,
          fmaf(Sx, w0b.z, fmaf(Sy, w1b.z, a1.z)) * inv,
          fmaf(Sx, w0b.w, fmaf(Sy, w1b.w, a1.w)) * inv);
}

// ---------------- attn layer 1: one block = one (dst-chunk, type) ----------------
__global__ void __launch_bounds__(128) attn1_kernel(const float* __restrict__ We) {
    int slot = blockIdx.y;                 // 0..4, type c_s2t[slot]
    __shared__ __align__(16) float sWe[128];
    if (threadIdx.x < 32)
        ((float4*)sWe)[threadIdx.x] =
            ((const float4*)(We + c_s2t[slot] * 128))[threadIdx.x];
    __syncthreads();

    int lane = threadIdx.x & 7;
    unsigned gmask = 0xFFu << (threadIdx.x & 24);
    int dst = blockIdx.x * 16 + (threadIdx.x >> 3);
    bool valid = dst < NN;
    int d0 = valid ? dst : 0;

    float* O = c_p2o[slot] ? g_O2 : g_O1;
    attn_type_atomic(slot, sWe, d0, valid, lane, gmask, O);
}

// ---------------- attn layer 2: one block = one (dst-chunk, type) ----------------
__global__ void __launch_bounds__(128) attn2_kernel(const float* __restrict__ We) {
    int ti = blockIdx.y;                   // 0..2
    int slot = c_a2s[ti];
    __shared__ __align__(16) float sWe[128];
    if (threadIdx.x < 32)
        ((float4*)sWe)[threadIdx.x] =
            ((const float4*)(We + (9 + c_a2t[ti]) * 128))[threadIdx.x];
    __syncthreads();

    int lane = threadIdx.x & 7;
    unsigned gmask = 0xFFu << (threadIdx.x & 24);
    int dst = blockIdx.x * 16 + (threadIdx.x >> 3);
    bool valid = dst < NN;
    int d0 = valid ? dst : 0;

    attn_type_atomic(slot, sWe, d0, valid, lane, gmask, g_OUT2);
}

// ---------------- final: relu(OUT2) @ lin_W + lin_b ----------------
__global__ void __launch_bounds__(256) final_kernel(
    const float* __restrict__ linW, const float* __restrict__ linb, float* __restrict__ out)
{
    __shared__ __align__(16) float4 sLW[64];
    if (threadIdx.x < 64) sLW[threadIdx.x] = *(const float4*)(linW + threadIdx.x * 4);
    __syncthreads();
    int lane = threadIdx.x & 7;
    int row = blockIdx.x * 32 + (threadIdx.x >> 3);
    if (row >= NN) return;
    const float* X = g_OUT2 + (size_t)row * 64 + lane * 8;
    float4 acc = make_float4(0.f, 0.f, 0.f, 0.f);
    #pragma unroll
    for (int c = 0; c < 8; c++) {
        float x = fmaxf(X[c], 0.f);
        float4 wv = sLW[lane * 8 + c];
        acc.x = fmaf(x, wv.x, acc.x);
        acc.y = fmaf(x, wv.y, acc.y);
        acc.z = fmaf(x, wv.z, acc.z);
        acc.w = fmaf(x, wv.w, acc.w);
    }
    #pragma unroll
    for (int off = 1; off < 8; off <<= 1) {
        acc.x += __shfl_xor_sync(0xffffffffu, acc.x, off);
        acc.y += __shfl_xor_sync(0xffffffffu, acc.y, off);
        acc.z += __shfl_xor_sync(0xffffffffu, acc.z, off);
        acc.w += __shfl_xor_sync(0xffffffffu, acc.w, off);
    }
    if (lane == 0) {
        float4 b = *(const float4*)linb;
        acc.x += b.x; acc.y += b.y; acc.z += b.z; acc.w += b.w;
        *(float4*)(out + row * 4) = acc;
    }
}

// ---------------- launcher: CSR build on side stream (proven-good) ----------------
extern "C" void kernel_launch(void* const* d_in, const int* in_sizes, int n_in,
                              void* d_out, int out_size) {
    (void)in_sizes; (void)n_in; (void)out_size;
    const float* x0 = (const float*)d_in[0];
    const float* x1 = (const float*)d_in[1];
    const float* x2 = (const float*)d_in[2];
    const float* x3 = (const float*)d_in[3];
    const int*   EI = (const int*)d_in[4];
    const float* EA = (const float*)d_in[5];
    const float* Wq = (const float*)d_in[6];
    const float* bq = (const float*)d_in[7];
    const float* Wk = (const float*)d_in[8];
    const float* bk = (const float*)d_in[9];
    const float* Wv = (const float*)d_in[10];
    const float* bv = (const float*)d_in[11];
    const float* We = (const float*)d_in[12];
    const float* Ws = (const float*)d_in[13];
    const float* bs = (const float*)d_in[14];
    const float* lW = (const float*)d_in[15];
    const float* lb = (const float*)d_in[16];
    float* out = (float*)d_out;

    const int ROWB = (NN + 127) / 128;   // 391
    const int EB   = (NEE + 255) / 256;  // 977
    const int DB   = (NN + 15) / 16;     // 3125

    static cudaStream_t s2 = nullptr;
    static cudaEvent_t eFork = nullptr, eJoin = nullptr;
    if (s2 == nullptr) {
        cudaStreamCreateWithFlags(&s2, cudaStreamNonBlocking);
        cudaEventCreateWithFlags(&eFork, cudaEventDisableTiming);
        cudaEventCreateWithFlags(&eJoin, cudaEventDisableTiming);
    }

    init_kernel<<<245, 256>>>();                                             // 0 (main)
    cudaEventRecord(eFork, 0);
    cudaStreamWaitEvent(s2, eFork, 0);

    count_kernel<<<dim3(EB, 5), 256, 0, s2>>>(EI);                           // 1
    scan1_kernel<<<dim3(NB, 5), 512, 0, s2>>>();                             // 2
    gemm_kernel<<<dim3(ROWB, 17), 128>>>(x0, x1, x2, x3, Wq, bq, Wk, bk,
                                         Wv, bv, Ws, bs, 0);                 // 3 (main, profiled)
    scan3_kernel<<<dim3(NB, 5), 512, 0, s2>>>();                             // 4
    scatter_kernel<<<dim3(EB, 5), 256, 0, s2>>>(EI, EA);                     // 5
    cudaEventRecord(eJoin, s2);
    cudaStreamWaitEvent(0, eJoin, 0);

    attn1_kernel<<<dim3(DB, 5), 128>>>(We);                                  // 6
    gemm_kernel<<<dim3(ROWB, 10), 128>>>(x0, x1, x2, x3, Wq, bq, Wk, bk,
                                         Wv, bv, Ws, bs, 1);                 // 7
    attn2_kernel<<<dim3(DB, 3), 128>>>(We);                                  // 8
    final_kernel<<<(NN + 31) / 32, 256>>>(lW, lb, out);                      // 9
}